// round 6
// baseline (speedup 1.0000x reference)
#include <cuda_runtime.h>

// Problem constants
#define TBm 32       // T*B
#define Cc  256
#define Nn  196
#define Hh  16
#define Dd  16
#define HDd 1024
#define Jj  (TBm*Nn)     // 6272
#define EPSV 1e-5f

// ---------------- scratch (static device globals; no runtime alloc) -------------
__device__ float g_z [TBm*HDd*Nn];   // GEMM output scratch (max 1024 channels)
__device__ float g_h [TBm*HDd*Nn];   // h spikes (m1 output)
__device__ float g_s [TBm*Cc*Nn];    // attention o spikes (float 0/1)
__device__ float g_x1[TBm*Cc*Nn];
__device__ float g_y1[TBm*Cc*Nn];
__device__ float g_cur[TBm*Cc*Nn];
__device__ unsigned int g_qm[TBm*Hh*Nn];
__device__ unsigned int g_km[TBm*Hh*Nn];
__device__ unsigned int g_vm[TBm*Hh*Nn];
__device__ float g_mu[HDd];
__device__ float g_rs[HDd];

// ---------------- GEMM: out[m,d,n] = sum_c W[d,c]*A[m,c,n] (+opt second pair, +bias) ----
// Exact fp32, strictly ascending-k single-accumulator FMA per output element
// (bitwise identical to cuBLAS SIMT SGEMM / Triton fp32 dot accumulation).
__global__ __launch_bounds__(256) void gemm_k(
    const float* __restrict__ A, const float* __restrict__ W,
    const float* __restrict__ bias, const float* __restrict__ bias2,
    float* __restrict__ out, int Cin, int Cout,
    const float* __restrict__ A2, const float* __restrict__ W2)
{
    __shared__ float As[16][68];
    __shared__ float Bs[16][68];
    const int t  = threadIdx.x;
    const int d0 = blockIdx.y * 64;
    const int j0 = blockIdx.x * 64;
    const int tx = t & 15;
    const int ty = t >> 4;
    const int jj = t & 63;
    const int kr = t >> 6;            // 0..3
    const int jB = j0 + jj;
    const int mB = jB / Nn;
    const int nB = jB - mB * Nn;
    const int kc = t & 15;
    const int ir = t >> 4;            // 0..15

    float acc[2][4][4];
#pragma unroll
    for (int p = 0; p < 2; p++)
#pragma unroll
        for (int i = 0; i < 4; i++)
#pragma unroll
            for (int q = 0; q < 4; q++) acc[p][i][q] = 0.f;

    const int npass = A2 ? 2 : 1;
    for (int pass = 0; pass < npass; ++pass) {
        const float* Ain = pass ? A2 : A;
        const float* Win = pass ? W2 : W;
        const float* aptr = Ain + (size_t)mB * Cin * Nn + nB;
        for (int c0 = 0; c0 < Cin; c0 += 16) {
            __syncthreads();
#pragma unroll
            for (int r = 0; r < 4; ++r)
                As[kc][ir + 16*r] = Win[(size_t)(d0 + ir + 16*r) * Cin + c0 + kc];
#pragma unroll
            for (int r = 0; r < 4; ++r)
                Bs[kr + 4*r][jj] = aptr[(size_t)(c0 + kr + 4*r) * Nn];
            __syncthreads();
#pragma unroll
            for (int k = 0; k < 16; ++k) {
                float4 a4 = *reinterpret_cast<const float4*>(&As[k][ty * 4]);
                float a[4] = {a4.x, a4.y, a4.z, a4.w};
                float b[4];
#pragma unroll
                for (int q = 0; q < 4; q++) b[q] = Bs[k][tx + 16*q];
#pragma unroll
                for (int i = 0; i < 4; i++)
#pragma unroll
                    for (int q = 0; q < 4; q++)
                        acc[pass][i][q] = __fmaf_rn(a[i], b[q], acc[pass][i][q]);
            }
        }
    }
#pragma unroll
    for (int q = 0; q < 4; q++) {
        int jw = j0 + tx + 16*q;
        int mo = jw / Nn;
        int no = jw - mo * Nn;
        float* obase = out + (size_t)mo * Cout * Nn + no;
#pragma unroll
        for (int i = 0; i < 4; i++) {
            int dd = d0 + ty * 4 + i;
            float v = acc[0][i][q];
            if (bias)  v = __fadd_rn(v, bias[dd]);
            if (A2) {
                float v2 = acc[1][i][q];
                if (bias2) v2 = __fadd_rn(v2, bias2[dd]);
                v = __fadd_rn(v, v2);
            }
            obase[(size_t)dd * Nn] = v;
        }
    }
}

// ---------------- XLA:GPU row-reduction replica ----------------
// Shape [depth=32, height=C, width=196], reduced {depth, width}.
// Config: num_threads_x = RoundUpTo(196,32) = 224 (7 warps), one block per channel.
// Thread t owns column n=t: partial = sum over m ascending (single acc).
// Warp butterfly shfl_down 16/8/4/2/1; leaders -> smem; warp0 loads
// (lane<7 ? partial : 0) and butterflies again; lane0 holds the total.
__global__ __launch_bounds__(224) void stats_mean_k(const float* __restrict__ z, int Cout)
{
    const int c = blockIdx.x;
    const int t = threadIdx.x;
    __shared__ float sw[7];
    float p = 0.f;
    if (t < Nn) {
        const float* base = z + (size_t)c * Nn + t;
        for (int m = 0; m < TBm; ++m)
            p = __fadd_rn(p, base[(size_t)m * Cout * Nn]);
    }
#pragma unroll
    for (int off = 16; off; off >>= 1)
        p = __fadd_rn(p, __shfl_down_sync(0xFFFFFFFFu, p, off));
    int lane = t & 31, w = t >> 5;
    if (!lane) sw[w] = p;
    __syncthreads();
    if (w == 0) {
        float v = (lane < 7) ? sw[lane] : 0.f;
#pragma unroll
        for (int off = 16; off; off >>= 1)
            v = __fadd_rn(v, __shfl_down_sync(0xFFFFFFFFu, v, off));
        if (!lane) g_mu[c] = __fdiv_rn(v, 6272.f);
    }
}

// Second fused reduce: sum over (z - mu)^2, same tree; then var = sum/6272,
// rs = rsqrtf(var + eps)  [libdevice __nv_rsqrtf, same function XLA links].
__global__ __launch_bounds__(224) void stats_var_k(const float* __restrict__ z, int Cout)
{
    const int c = blockIdx.x;
    const int t = threadIdx.x;
    __shared__ float sw[7];
    const float mu = g_mu[c];
    float p = 0.f;
    if (t < Nn) {
        const float* base = z + (size_t)c * Nn + t;
        for (int m = 0; m < TBm; ++m) {
            float dv = __fsub_rn(base[(size_t)m * Cout * Nn], mu);
            p = __fadd_rn(p, __fmul_rn(dv, dv));
        }
    }
#pragma unroll
    for (int off = 16; off; off >>= 1)
        p = __fadd_rn(p, __shfl_down_sync(0xFFFFFFFFu, p, off));
    int lane = t & 31, w = t >> 5;
    if (!lane) sw[w] = p;
    __syncthreads();
    if (w == 0) {
        float v = (lane < 7) ? sw[lane] : 0.f;
#pragma unroll
        for (int off = 16; off; off >>= 1)
            v = __fadd_rn(v, __shfl_down_sync(0xFFFFFFFFu, v, off));
        if (!lane) {
            float var = __fdiv_rn(v, 6272.f);
            g_rs[c] = rsqrtf(__fadd_rn(var, EPSV));
        }
    }
}

// BN affine exactly as reference: ((g*(z-mu))*rs)+b, separate roundings
__device__ __forceinline__ float bn_val(float v, float g, float mu, float rs, float b)
{
    return __fadd_rn(__fmul_rn(__fmul_rn(g, __fsub_rn(v, mu)), rs), b);
}

// ---------------- BN+LIF -> 16-bit head mask (q/k/v) ----------------
__global__ __launch_bounds__(256) void spike_mask_k(
    const float* __restrict__ z, const float* __restrict__ g,
    const float* __restrict__ b, unsigned int* __restrict__ mask)
{
    int idx = blockIdx.x * 256 + threadIdx.x;     // exactly TBm*Hh*Nn threads
    int n  = idx % Nn;
    int th = idx / Nn;
    int h  = th & 15;
    int m  = th >> 4;
    const float* zb = z + (size_t)m * Cc * Nn + (size_t)h * Dd * Nn + n;
    unsigned int msk = 0;
#pragma unroll
    for (int d = 0; d < Dd; ++d) {
        int c = h * Dd + d;
        float bn = bn_val(zb[(size_t)d * Nn], g[c], g_mu[c], g_rs[c], b[c]);
        if (bn >= 1.f) msk |= (1u << d);
    }
    mask[idx] = msk;
}

// ---------------- BN+LIF elementwise (optional residual add) ----------------
__global__ __launch_bounds__(256) void spike_bn_k(
    const float* __restrict__ z, const float* __restrict__ g,
    const float* __restrict__ b, const float* __restrict__ addsrc,
    float* __restrict__ out, int Cout)
{
    int idx = blockIdx.x * 256 + threadIdx.x;
    int c = (idx / Nn) % Cout;
    float bn = bn_val(z[idx], g[c], g_mu[c], g_rs[c], b[c]);
    float s = (bn >= 1.f) ? 1.f : 0.f;
    out[idx] = addsrc ? __fadd_rn(addsrc[idx], s) : s;
}

// ---------------- cur = LIF(zx+zy, 1.0) ----------------
__global__ __launch_bounds__(256) void cur_k(const float* __restrict__ z, float* __restrict__ cur)
{
    int idx = blockIdx.x * 256 + threadIdx.x;
    cur[idx] = (z[idx] >= 1.f) ? 1.f : 0.f;
}

// ---------------- attention: exact integer bit-packed (order-independent) -------
__global__ __launch_bounds__(224) void attn_k(
    const unsigned int* __restrict__ qm, const unsigned int* __restrict__ km,
    const unsigned int* __restrict__ vm, const float* __restrict__ P,
    int use_rpb, float* __restrict__ out)
{
    __shared__ unsigned int skm[Nn];
    __shared__ unsigned long long sv[Nn][4];
    __shared__ float sP[29 * 29];
    const int tbh = blockIdx.x;
    const int mb = tbh >> 4;
    const int h  = tbh & 15;
    const int base = tbh * Nn;
    const int t = threadIdx.x;
    for (int i = t; i < Nn; i += 224) {
        skm[i] = km[base + i];
        unsigned int v = vm[base + i];
#pragma unroll
        for (int w = 0; w < 4; ++w) {
            unsigned long long xL = 0;
#pragma unroll
            for (int d = 0; d < 4; ++d)
                xL |= (unsigned long long)((v >> (w * 4 + d)) & 1u) << (16 * d);
            sv[i][w] = xL;
        }
    }
    if (use_rpb)
        for (int i = t; i < 841; i += 224) sP[i] = P[i];
    __syncthreads();
    if (t >= Nn) return;

    const unsigned int q = qm[base + t];
    unsigned long long acc0 = 0, acc1 = 0, acc2 = 0, acc3 = 0;
    if (use_rpb) {
        const int ni = t / 14, nj = t - (t / 14) * 14;
        const float* prow = sP + (ni + 14) * 29 + (nj + 14);
        int m = 0;
        for (int ki = 0; ki < 14; ++ki) {
            const float* pr = prow - ki * 29;
#pragma unroll
            for (int kj = 0; kj < 14; ++kj, ++m) {
                int cnt = __popc(q & skm[m]);
                if (__fadd_rn((float)cnt, pr[-kj]) >= 1.f) {
                    acc0 += sv[m][0]; acc1 += sv[m][1];
                    acc2 += sv[m][2]; acc3 += sv[m][3];
                }
            }
        }
    } else {
#pragma unroll 4
        for (int m = 0; m < Nn; ++m) {
            unsigned long long c = (unsigned long long)__popc(q & skm[m]);
            acc0 += sv[m][0] * c; acc1 += sv[m][1] * c;
            acc2 += sv[m][2] * c; acc3 += sv[m][3] * c;
        }
    }
    float* obase = out + (size_t)mb * Cc * Nn + (size_t)h * Dd * Nn + t;
    unsigned long long accs[4] = {acc0, acc1, acc2, acc3};
#pragma unroll
    for (int w = 0; w < 4; ++w)
#pragma unroll
        for (int d4 = 0; d4 < 4; ++d4) {
            int cv = (int)((accs[w] >> (16 * d4)) & 0xFFFFULL);
            obase[(size_t)(w * 4 + d4) * Nn] = (cv >= 2) ? 1.f : 0.f;
        }
}

// ---------------- host orchestration ----------------
extern "C" void kernel_launch(void* const* d_in, const int* in_sizes, int n_in,
                              void* d_out, int out_size)
{
    const float* x     = (const float*)d_in[0];
    const float* y     = (const float*)d_in[1];
    const float* av_w  = (const float*)d_in[2];
    const float* av_g  = (const float*)d_in[3];
    const float* av_b  = (const float*)d_in[4];
    const float* va_w  = (const float*)d_in[5];
    const float* va_g  = (const float*)d_in[6];
    const float* va_b  = (const float*)d_in[7];
    const float* P_rpb = (const float*)d_in[8];
    const float* fc1_w = (const float*)d_in[9];
    const float* fc1_b = (const float*)d_in[10];
    const float* fc2_w = (const float*)d_in[11];
    const float* fc2_b = (const float*)d_in[12];
    const float* m1_w  = (const float*)d_in[13];
    const float* m1_b  = (const float*)d_in[14];
    const float* m1_g  = (const float*)d_in[15];
    const float* m1_bb = (const float*)d_in[16];
    const float* m2_w  = (const float*)d_in[17];
    const float* m2_b  = (const float*)d_in[18];
    const float* m2_g  = (const float*)d_in[19];
    const float* m2_bb = (const float*)d_in[20];
    float* out = (float*)d_out;

    float *zb, *hb, *sb, *x1b, *y1b, *curb;
    unsigned int *qmb, *kmb, *vmb;
    cudaGetSymbolAddress((void**)&zb,  g_z);
    cudaGetSymbolAddress((void**)&hb,  g_h);
    cudaGetSymbolAddress((void**)&sb,  g_s);
    cudaGetSymbolAddress((void**)&x1b, g_x1);
    cudaGetSymbolAddress((void**)&y1b, g_y1);
    cudaGetSymbolAddress((void**)&curb, g_cur);
    cudaGetSymbolAddress((void**)&qmb, g_qm);
    cudaGetSymbolAddress((void**)&kmb, g_km);
    cudaGetSymbolAddress((void**)&vmb, g_vm);

    const int nC  = TBm * Cc * Nn;     // 1,605,632
    const int nHD = TBm * HDd * Nn;    // 6,422,528

    auto gemm = [&](const float* A, const float* W, const float* bias, const float* bias2,
                    float* o, int Cin, int Cout, const float* A2, const float* W2) {
        dim3 grid(98, Cout / 64);
        gemm_k<<<grid, 256>>>(A, W, bias, bias2, o, Cin, Cout, A2, W2);
    };

    auto stats = [&](const float* z, int Cout) {
        stats_mean_k<<<Cout, 224>>>(z, Cout);
        stats_var_k<<<Cout, 224>>>(z, Cout);
    };

    auto sca = [&](const float* srcq, const float* srckv,
                   const float* W, const float* G, const float* Bt,
                   const float* rpb, const float* addbase, float* outbuf) {
        gemm(srcq, W, nullptr, nullptr, zb, Cc, Cc, nullptr, nullptr);
        stats(zb, Cc);
        spike_mask_k<<<392, 256>>>(zb, G, Bt, qmb);

        gemm(srckv, W + Cc * Cc, nullptr, nullptr, zb, Cc, Cc, nullptr, nullptr);
        stats(zb, Cc);
        spike_mask_k<<<392, 256>>>(zb, G + Cc, Bt + Cc, kmb);

        gemm(srckv, W + 2 * Cc * Cc, nullptr, nullptr, zb, Cc, Cc, nullptr, nullptr);
        stats(zb, Cc);
        spike_mask_k<<<392, 256>>>(zb, G + 2 * Cc, Bt + 2 * Cc, vmb);

        attn_k<<<TBm * Hh, 224>>>(qmb, kmb, vmb, rpb, rpb != nullptr, sb);

        gemm(sb, W + 3 * Cc * Cc, nullptr, nullptr, zb, Cc, Cc, nullptr, nullptr);
        stats(zb, Cc);
        spike_bn_k<<<nC / 256, 256>>>(zb, G + 3 * Cc, Bt + 3 * Cc, addbase, outbuf, Cc);
    };

    // x1 = x + sca(x, y, av);  y1 = y + sca(y, x, va, rpb)
    sca(x, y, av_w, av_g, av_b, nullptr, x, x1b);
    sca(y, x, va_w, va_g, va_b, P_rpb, y, y1b);

    // cur = LIF(fc1(x1) + fc2(y1))
    gemm(x1b, fc1_w, fc1_b, fc2_b, zb, Cc, Cc, y1b, fc2_w);
    cur_k<<<nC / 256, 256>>>(zb, curb);

    // h = LIF(BN(m1(cur)))
    gemm(curb, m1_w, m1_b, nullptr, zb, Cc, HDd, nullptr, nullptr);
    stats(zb, HDd);
    spike_bn_k<<<nHD / 256, 256>>>(zb, m1_g, m1_bb, nullptr, hb, HDd);

    // out = cur + LIF(BN(m2(h)))
    gemm(hb, m2_w, m2_b, nullptr, zb, HDd, Cc, nullptr, nullptr);
    stats(zb, Cc);
    spike_bn_k<<<nC / 256, 256>>>(zb, m2_g, m2_bb, curb, out, Cc);

    (void)in_sizes; (void)n_in; (void)out_size;
}